// round 3
// baseline (speedup 1.0000x reference)
#include <cuda_runtime.h>
#include <cstdint>
#include <cstddef>

// LSTM_LSTM_455266533595 : 2-layer LSTM encoder (B=256,T=336,H=1024) +
// 96-step 2-layer decoder with FC feedback.
// SINGLE persistent kernel (one graph node — avoids the 2MB graph-upload
// residue that failed R1). 128 co-resident CTAs, software grid barrier
// between recurrence phases. fp32 SIMT GEMM with packed fma.rn.f32x2.

#define Bsz    256
#define Hdim   1024
#define Tlen   336
#define OUTLEN 96
#define BT     64      // batch tile per CTA
#define NT     32      // hidden units per CTA (x4 gates = 128 gate cols)
#define GT     128     // gate columns per CTA
#define KC     32      // K chunk
#define KCP    34      // padded K chunk (conflict-free f32x2 reads)
#define BH     (Bsz*Hdim)
#define NCTA   128     // (4 batch tiles) x (32 hidden tiles) — all co-resident

// ---------------- persistent device state (no allocations allowed) ----------
__device__ float g_h0[2][BH];
__device__ float g_h1[2][BH];
__device__ float g_c0[BH];
__device__ float g_c1[BH];
__device__ float g_xt[Bsz];
__device__ unsigned g_cnt;   // zero-initialized; each barrier leaves it at 0
__device__ unsigned g_gen;   // monotonically increasing generation counter

__device__ __forceinline__ float sigmoidf_(float x) { return 1.0f / (1.0f + expf(-x)); }

// ---------------------------------------------------------------------------
// Grid-wide barrier: sense via generation counter. All 128 CTAs are resident
// (grid < #SMs), so spinning is deadlock-free. Leader resets the count BEFORE
// releasing the generation bump, so early re-arrivals at the next barrier
// cannot race the reset.
// ---------------------------------------------------------------------------
__device__ __forceinline__ void grid_sync() {
    __syncthreads();
    if (threadIdx.x == 0) {
        __threadfence();                                   // release prior writes
        unsigned g = *(volatile unsigned*)&g_gen;          // read BEFORE arriving
        unsigned a = atomicAdd(&g_cnt, 1u);
        if (a == NCTA - 1) {
            atomicExch(&g_cnt, 0u);
            __threadfence();
            atomicAdd(&g_gen, 1u);
        } else {
            while (*(volatile unsigned*)&g_gen == g) { __nanosleep(64); }
        }
        __threadfence();                                   // acquire
    }
    __syncthreads();
}

// ---------------------------------------------------------------------------
// One LSTM cell phase for this CTA's (64 batch x 32 hidden) tile.
//   gates = [A1 @ W1^T] + [A2 @ W2^T] + bias + xs[b]*wih   (A1/xs optional)
// Thread (tx=tid&15, ty=tid>>4) owns a 4(m) x 8(gate-col) register tile;
// gate-col(j) = 16*j + tx  ->  gate = j>>1, hidden = (j&1)*16 + tx, so the
// full i/f/g/o set for each (m, hidden) lives in one thread's registers.
// ---------------------------------------------------------------------------
__device__ __noinline__ void lstm_phase(
    const float* __restrict__ A1, const float* __restrict__ W1,
    const float* __restrict__ A2, const float* __restrict__ W2,
    const float* __restrict__ bias,
    const float* __restrict__ xs, int xs_stride,
    const float* __restrict__ wih,
    float* c, float* __restrict__ h_out)
{
    __shared__ float As[BT][KCP];
    __shared__ float Bs[GT][KCP];

    const int tid = threadIdx.x;
    const int tx = tid & 15;
    const int ty = tid >> 4;
    const int m0 = (blockIdx.x & 3) * BT;
    const int n0 = (blockIdx.x >> 2) * NT;

    unsigned long long acc[4][8];   // f32x2 accumulators (.x even-k, .y odd-k)
#pragma unroll
    for (int i = 0; i < 4; i++)
#pragma unroll
        for (int j = 0; j < 8; j++) acc[i][j] = 0ull;

    const float* Ap[2] = { A1, A2 };
    const float* Wp[2] = { W1, W2 };

#pragma unroll 1
    for (int pass = 0; pass < 2; pass++) {
        const float* A = Ap[pass];
        if (A == nullptr) continue;
        const float* W = Wp[pass];

#pragma unroll 1
        for (int k0 = 0; k0 < Hdim; k0 += KC) {
            __syncthreads();
            // A tile: 64 rows x 32 k (512 float4, 2/thread)
#pragma unroll
            for (int j = 0; j < 2; j++) {
                int lin = tid + j * 256;
                int row = lin >> 3;
                int kq  = lin & 7;
                float4 v = *reinterpret_cast<const float4*>(
                    A + (size_t)(m0 + row) * Hdim + k0 + kq * 4);
                float2* d = reinterpret_cast<float2*>(&As[row][kq * 4]);
                d[0] = make_float2(v.x, v.y);
                d[1] = make_float2(v.z, v.w);
            }
            // W tile: 128 gate-cols x 32 k (1024 float4, 4/thread)
#pragma unroll
            for (int j = 0; j < 4; j++) {
                int lin = tid + j * 256;
                int cc2 = lin >> 3;
                int kq  = lin & 7;
                int gi  = ((cc2 >> 5) << 10) + n0 + (cc2 & 31);  // gate*1024 + n
                float4 v = *reinterpret_cast<const float4*>(
                    W + (size_t)gi * Hdim + k0 + kq * 4);
                float2* d = reinterpret_cast<float2*>(&Bs[cc2][kq * 4]);
                d[0] = make_float2(v.x, v.y);
                d[1] = make_float2(v.z, v.w);
            }
            __syncthreads();

#pragma unroll
            for (int kk = 0; kk < KC / 2; kk++) {
                unsigned long long a2[4], b2[8];
#pragma unroll
                for (int i = 0; i < 4; i++)
                    a2[i] = *reinterpret_cast<const unsigned long long*>(&As[ty * 4 + i][kk * 2]);
#pragma unroll
                for (int j = 0; j < 8; j++)
                    b2[j] = *reinterpret_cast<const unsigned long long*>(&Bs[j * 16 + tx][kk * 2]);
#pragma unroll
                for (int i = 0; i < 4; i++)
#pragma unroll
                    for (int j = 0; j < 8; j++)
                        asm("fma.rn.f32x2 %0, %1, %2, %0;"
                            : "+l"(acc[i][j]) : "l"(a2[i]), "l"(b2[j]));
            }
        }
    }

    // pointwise LSTM update (full gate set in registers)
    float bI[2], bF[2], bG[2], bO[2], wI[2], wF[2], wG[2], wO[2];
#pragma unroll
    for (int h = 0; h < 2; h++) {
        int n = n0 + h * 16 + tx;
        bI[h] = bias[n];
        bF[h] = bias[Hdim + n];
        bG[h] = bias[2 * Hdim + n];
        bO[h] = bias[3 * Hdim + n];
        if (wih) {
            wI[h] = wih[n];
            wF[h] = wih[Hdim + n];
            wG[h] = wih[2 * Hdim + n];
            wO[h] = wih[3 * Hdim + n];
        } else {
            wI[h] = wF[h] = wG[h] = wO[h] = 0.0f;
        }
    }
#pragma unroll
    for (int i = 0; i < 4; i++) {
        int m = m0 + ty * 4 + i;
        float xv = xs ? xs[(size_t)m * xs_stride] : 0.0f;
#pragma unroll
        for (int h = 0; h < 2; h++) {
            float2 vi = *reinterpret_cast<float2*>(&acc[i][0 + h]);
            float2 vf = *reinterpret_cast<float2*>(&acc[i][2 + h]);
            float2 vg = *reinterpret_cast<float2*>(&acc[i][4 + h]);
            float2 vo = *reinterpret_cast<float2*>(&acc[i][6 + h]);
            float pi = vi.x + vi.y + bI[h] + xv * wI[h];
            float pf = vf.x + vf.y + bF[h] + xv * wF[h];
            float pg = vg.x + vg.y + bG[h] + xv * wG[h];
            float po = vo.x + vo.y + bO[h] + xv * wO[h];
            int idx = m * Hdim + n0 + h * 16 + tx;
            float cc = c[idx];
            float ig = sigmoidf_(pi);
            float fg = sigmoidf_(pf);
            float og = sigmoidf_(po);
            float gg = tanhf(pg);
            float cn = fg * cc + ig * gg;
            float hn = og * tanhf(cn);
            c[idx]     = cn;
            h_out[idx] = hn;
        }
    }
}

// FC head phase: CTAs 0..31, one warp per batch row (8 rows/CTA).
__device__ __forceinline__ void fc_phase(
    const float* __restrict__ h1, const float* __restrict__ fcW,
    const float* __restrict__ fcb, float* __restrict__ out,
    float* __restrict__ xt, int s)
{
    if (blockIdx.x >= 32) return;
    int warp = threadIdx.x >> 5;
    int lane = threadIdx.x & 31;
    int b = blockIdx.x * 8 + warp;
    float sum = 0.0f;
    const float* hr = h1 + (size_t)b * Hdim;
#pragma unroll 8
    for (int k = lane; k < Hdim; k += 32) sum += hr[k] * fcW[k];
#pragma unroll
    for (int off = 16; off > 0; off >>= 1)
        sum += __shfl_down_sync(0xFFFFFFFFu, sum, off);
    if (lane == 0) {
        float y = sum + fcb[0];
        out[(size_t)b * OUTLEN + s] = y;
        xt[b] = y;
    }
}

// ---------------------------------------------------------------------------
__global__ void __launch_bounds__(256) lstm_persistent_kernel(
    const float* __restrict__ x,
    const float* __restrict__ enc_Wih0, const float* __restrict__ enc_Whh0,
    const float* __restrict__ enc_b0,
    const float* __restrict__ enc_Wih1, const float* __restrict__ enc_Whh1,
    const float* __restrict__ enc_b1,
    const float* __restrict__ dec_Wih0, const float* __restrict__ dec_Whh0,
    const float* __restrict__ dec_b0,
    const float* __restrict__ dec_Wih1, const float* __restrict__ dec_Whh1,
    const float* __restrict__ dec_b1,
    const float* __restrict__ fc_W, const float* __restrict__ fc_b,
    float* __restrict__ out)
{
    float* h0 = &g_h0[0][0];
    float* h1 = &g_h1[0][0];
    float* c0 = g_c0;
    float* c1 = g_c1;
    float* xt = g_xt;

    // ---- init: zero read-side ping buffers + cell states; seed feedback ----
    {
        const int per = BH / NCTA;              // 2048 floats per CTA
        float4 z = make_float4(0.f, 0.f, 0.f, 0.f);
        int base = blockIdx.x * per;
#pragma unroll
        for (int j = 0; j < per / (256 * 4); j++) {      // 2 float4 per thread
            int i = base + (threadIdx.x + j * 256) * 4;
            *reinterpret_cast<float4*>(&g_h0[0][i]) = z;
            *reinterpret_cast<float4*>(&g_h1[0][i]) = z;
            *reinterpret_cast<float4*>(&g_c0[i]) = z;
            *reinterpret_cast<float4*>(&g_c1[i]) = z;
        }
        if (blockIdx.x == 0)
            xt[threadIdx.x] = x[(size_t)threadIdx.x * Tlen + (Tlen - 1)];
    }
    grid_sync();

    int p0 = 0, p1 = 0;

    // -------- encoder --------
#pragma unroll 1
    for (int t = 0; t < Tlen; t++) {
        lstm_phase(nullptr, nullptr,
                   h0 + (size_t)p0 * BH, enc_Whh0, enc_b0,
                   x + t, Tlen, enc_Wih0,
                   c0, h0 + (size_t)(p0 ^ 1) * BH);
        p0 ^= 1;
        grid_sync();
        lstm_phase(h0 + (size_t)p0 * BH, enc_Wih1,
                   h1 + (size_t)p1 * BH, enc_Whh1, enc_b1,
                   nullptr, 0, nullptr,
                   c1, h1 + (size_t)(p1 ^ 1) * BH);
        p1 ^= 1;
        grid_sync();
    }

    // -------- decoder (96 autoregressive steps) --------
#pragma unroll 1
    for (int s = 0; s < OUTLEN; s++) {
        lstm_phase(nullptr, nullptr,
                   h0 + (size_t)p0 * BH, dec_Whh0, dec_b0,
                   xt, 1, dec_Wih0,
                   c0, h0 + (size_t)(p0 ^ 1) * BH);
        p0 ^= 1;
        grid_sync();
        lstm_phase(h0 + (size_t)p0 * BH, dec_Wih1,
                   h1 + (size_t)p1 * BH, dec_Whh1, dec_b1,
                   nullptr, 0, nullptr,
                   c1, h1 + (size_t)(p1 ^ 1) * BH);
        p1 ^= 1;
        grid_sync();
        fc_phase(h1 + (size_t)p1 * BH, fc_W, fc_b, out, xt, s);
        grid_sync();
    }
}

// ---------------------------------------------------------------------------
extern "C" void kernel_launch(void* const* d_in, const int* in_sizes, int n_in,
                              void* d_out, int out_size)
{
    (void)in_sizes; (void)n_in; (void)out_size;
    lstm_persistent_kernel<<<NCTA, 256>>>(
        (const float*)d_in[0],
        (const float*)d_in[1],  (const float*)d_in[2],  (const float*)d_in[3],
        (const float*)d_in[4],  (const float*)d_in[5],  (const float*)d_in[6],
        (const float*)d_in[7],  (const float*)d_in[8],  (const float*)d_in[9],
        (const float*)d_in[10], (const float*)d_in[11], (const float*)d_in[12],
        (const float*)d_in[13], (const float*)d_in[14],
        (float*)d_out);
}